// round 6
// baseline (speedup 1.0000x reference)
#include <cuda_runtime.h>
#include <math_constants.h>

#define NA    4     // anchors per block
#define GRID  64    // 64 * 4 = 256 anchors, single wave
#define NT    512   // threads per block (16 warps for latency hiding)
#define ROWW  132   // padded row stride (floats): conflict-free LDS.128

__device__ float        g_sum;
__device__ float        g_cnt;
__device__ unsigned int g_ticket;

extern __shared__ float semb[];   // 256 * ROWW floats = 135168 B (dynamic)

__global__ void __launch_bounds__(NT, 1)
triplet_fused(const float* __restrict__ emb,
              const int* __restrict__ labraw,
              float* __restrict__ out) {
    __shared__ float dkS[NA][260];      // d[ia, j] rows (260%32==4 -> conflict-free)
    __shared__ float pN[NT];            // partial norms  [half*256 + j]
    __shared__ float pD[NA][NT];        // partial dots
    __shared__ float normS[256];
    __shared__ int   labsh[256];
    __shared__ int   s_plist[NA * 256];
    __shared__ float s_wmax[NA][8];
    __shared__ float s_maxneg[NA];
    __shared__ int   s_is64;
    __shared__ int   s_npos;
    __shared__ float s_bsum;

    const int t    = threadIdx.x;
    const int lane = t & 31;
    const int w    = t >> 5;
    const int j    = t & 255;           // column this thread contributes to
    const int half = t >> 8;            // 0: c in [0,64), 1: c in [64,128)
    const int ib   = blockIdx.x * NA;

    if (t == 0) { s_is64 = 1; s_npos = 0; s_bsum = 0.f; }
    __syncthreads();

    // label dtype detect: int64 labels in [0,16) have zero high words.
    // Touches only the first 1KB — in-bounds for both int32[256] and int64[256].
    if (t < 128 && labraw[2 * t + 1] != 0) s_is64 = 0;   // benign race: all store 0

    // ---- coalesced staging of emb [256x128] into padded smem rows ----
    const float4* src = (const float4*)emb;
    #pragma unroll
    for (int k = 0; k < 16; k++) {
        int    idx4 = k * NT + t;          // consecutive lanes -> consecutive 16B
        float4 v    = src[idx4];
        int    r    = idx4 >> 5;
        int    c4   = idx4 & 31;
        *(float4*)(semb + r * ROWW + c4 * 4) = v;
    }
    if (t < 256) labsh[t] = s_is64 ? labraw[2 * t] : labraw[t];
    __syncthreads();

    // ---- phase 1: half-row partial dots (16-iter chains, rowT read once) ----
    const int c0 = half * 64;
    const float* rowT  = semb + j * ROWW + c0;
    const float* rowA0 = semb + (ib + 0) * ROWW + c0;
    const float* rowA1 = semb + (ib + 1) * ROWW + c0;
    const float* rowA2 = semb + (ib + 2) * ROWW + c0;
    const float* rowA3 = semb + (ib + 3) * ROWW + c0;

    float d0 = 0.f, d1 = 0.f, d2 = 0.f, d3 = 0.f, nj = 0.f;
    #pragma unroll
    for (int c = 0; c < 64; c += 4) {
        float4 a  = *(const float4*)(rowT + c);
        float4 b0 = *(const float4*)(rowA0 + c);   // broadcast
        float4 b1 = *(const float4*)(rowA1 + c);
        float4 b2 = *(const float4*)(rowA2 + c);
        float4 b3 = *(const float4*)(rowA3 + c);
        nj += a.x * a.x  + a.y * a.y  + a.z * a.z  + a.w * a.w;
        d0 += a.x * b0.x + a.y * b0.y + a.z * b0.z + a.w * b0.w;
        d1 += a.x * b1.x + a.y * b1.y + a.z * b1.z + a.w * b1.w;
        d2 += a.x * b2.x + a.y * b2.y + a.z * b2.z + a.w * b2.w;
        d3 += a.x * b3.x + a.y * b3.y + a.z * b3.z + a.w * b3.w;
    }
    pN[t] = nj;  pD[0][t] = d0;  pD[1][t] = d1;  pD[2][t] = d2;  pD[3][t] = d3;
    __syncthreads();

    // ---- combine halves, distances, positives, per-anchor maxNeg (t < 256) ----
    if (t < 256) {
        const float njf = pN[t] + pN[t + 256];
        normS[t] = njf;
    }
    __syncthreads();
    if (t < 256) {
        const float njf  = normS[t];
        const int   labt = labsh[t];
        #pragma unroll
        for (int a = 0; a < NA; a++) {
            const int   ia  = ib + a;
            const float dot = pD[a][t] + pD[a][t + 256];
            const float dv  = sqrtf(fmaxf(normS[ia] + njf - 2.f * dot, 1e-4f));
            dkS[a][t] = dv;
            const bool neg = (labt != labsh[ia]) || (t == ia);  // (1-pos) incl diag
            if (!neg) { int p = atomicAdd(&s_npos, 1); s_plist[p] = (a << 8) | t; }
            float m = neg ? dv : -CUDART_INF_F;
            #pragma unroll
            for (int off = 16; off; off >>= 1) m = fmaxf(m, __shfl_xor_sync(~0u, m, off));
            if (lane == 0) s_wmax[a][w] = m;
        }
    }
    __syncthreads();
    if (t < NA) {
        float mm = s_wmax[t][0];
        #pragma unroll
        for (int q = 1; q < 8; q++) mm = fmaxf(mm, s_wmax[t][q]);
        s_maxneg[t] = mm;
    }
    __syncthreads();

    // ---- phase 2: warp-cooperative semi-hard scan (16 warps) ----
    const int np = s_npos;
    float wsum = 0.f;
    for (int p = w; p < np; p += 16) {
        const int   e   = s_plist[p];
        const int   a   = e >> 8;
        const int   k   = e & 255;
        const int   ia  = ib + a;
        const int   la  = labsh[ia];
        const float dkk = dkS[a][k];
        float mg = CUDART_INF_F;     // min over negatives with d > dkk
        #pragma unroll
        for (int q = 0; q < 8; q++) {
            const int   jj = lane + 32 * q;          // one bank per lane
            const float dj = dkS[a][jj];
            const bool  ng = (labsh[jj] != la) || (jj == ia);
            mg = fminf(mg, (ng && dj > dkk) ? dj : CUDART_INF_F);
        }
        #pragma unroll
        for (int off = 16; off; off >>= 1) mg = fminf(mg, __shfl_xor_sync(~0u, mg, off));
        float v = (mg < CUDART_INF_F) ? (dkk - mg)           // semi-hard exists
                                      : (dkk - s_maxneg[a]); // fallback: easiest neg
        wsum += fmaxf(v + 1.0f, 0.f);                        // relu(semi_hard + MARGIN)
    }
    if (lane == 0 && wsum != 0.f) atomicAdd(&s_bsum, wsum);
    __syncthreads();

    // ---- last-block-done epilogue (single kernel) ----
    if (t == 0) {
        atomicAdd(&g_sum, s_bsum);
        atomicAdd(&g_cnt, (float)np);
        __threadfence();
        unsigned tk = atomicAdd(&g_ticket, 1u);
        if (tk == GRID - 1) {
            __threadfence();
            float s = atomicAdd(&g_sum, 0.f);
            float c = atomicAdd(&g_cnt, 0.f);
            out[0] = s / c;
            g_sum = 0.f;          // reset for next graph replay
            g_cnt = 0.f;
            __threadfence();
            g_ticket = 0u;
        }
    }
}

extern "C" void kernel_launch(void* const* d_in, const int* in_sizes, int n_in,
                              void* d_out, int out_size) {
    const float* emb    = (const float*)d_in[0];   // [256, 128] float32
    const int*   labraw = (const int*)d_in[1];     // [256] labels (int64/int32 detected)
    float* out = (float*)d_out;

    const int smem = 256 * ROWW * sizeof(float);   // 135168 B
    cudaFuncSetAttribute(triplet_fused, cudaFuncAttributeMaxDynamicSharedMemorySize, smem);
    triplet_fused<<<GRID, NT, smem>>>(emb, labraw, out);
}

// round 7
// speedup vs baseline: 2.0474x; 2.0474x over previous
#include <cuda_runtime.h>
#include <cuda_pipeline.h>
#include <math_constants.h>

#define NA    2     // anchors per block
#define GRID  128   // 128 * 2 = 256 anchors, single wave on 148+ SMs
#define NT    256
#define ROWW  132   // padded row stride (floats): conflict-free LDS.128

__device__ float        g_sum;
__device__ float        g_cnt;
__device__ unsigned int g_ticket;

extern __shared__ float semb[];   // 256 * ROWW floats = 135168 B (dynamic)

__global__ void __launch_bounds__(NT, 1)
triplet_fused(const float* __restrict__ emb,
              const int* __restrict__ labraw,
              float* __restrict__ out) {
    __shared__ float dkS[NA][260];     // d[ia, j] rows (260%32==4 -> conflict-free)
    __shared__ float normS[256];
    __shared__ int   labsh[256];
    __shared__ int   s_plist[NA * 256];
    __shared__ float s_wmax[NA][8];
    __shared__ float s_maxneg[NA];
    __shared__ int   s_is64;
    __shared__ int   s_npos;
    __shared__ float s_bsum;

    const int t    = threadIdx.x;
    const int lane = t & 31;
    const int w    = t >> 5;
    const int ib   = blockIdx.x * NA;

    if (t == 0) { s_is64 = 1; s_npos = 0; s_bsum = 0.f; }
    __syncthreads();

    // ---- async staging of emb [256x128] into padded smem rows (coalesced) ----
    const float4* src = (const float4*)emb;
    #pragma unroll
    for (int k = 0; k < 32; k++) {
        int idx4 = k * NT + t;            // consecutive lanes -> consecutive 16B
        int r    = idx4 >> 5;
        int c4   = idx4 & 31;
        __pipeline_memcpy_async(semb + r * ROWW + c4 * 4, src + idx4, 16);
    }
    __pipeline_commit();

    // label dtype detect while copies are in flight: int64 labels in [0,16)
    // have zero high words. Touches only the first 1KB (in-bounds for both).
    if (t < 128 && labraw[2 * t + 1] != 0) s_is64 = 0;   // benign race: all store 0
    __syncthreads();
    labsh[t] = s_is64 ? labraw[2 * t] : labraw[t];

    __pipeline_wait_prior(0);
    __syncthreads();

    // ---- phase 1: NA distance rows; rowT read once ----
    const float* rowT  = semb + t * ROWW;
    const float* rowA0 = semb + (ib + 0) * ROWW;
    const float* rowA1 = semb + (ib + 1) * ROWW;

    float d0 = 0.f, d1 = 0.f, nj = 0.f;
    #pragma unroll
    for (int c = 0; c < 128; c += 4) {
        float4 a  = *(const float4*)(rowT + c);
        float4 b0 = *(const float4*)(rowA0 + c);   // broadcast
        float4 b1 = *(const float4*)(rowA1 + c);
        nj += a.x * a.x  + a.y * a.y  + a.z * a.z  + a.w * a.w;
        d0 += a.x * b0.x + a.y * b0.y + a.z * b0.z + a.w * b0.w;
        d1 += a.x * b1.x + a.y * b1.y + a.z * b1.z + a.w * b1.w;
    }
    normS[t] = nj;
    __syncthreads();

    const float dotv[NA] = {d0, d1};
    const int   labt     = labsh[t];
    #pragma unroll
    for (int a = 0; a < NA; a++) {
        const int   ia = ib + a;
        const float dv = sqrtf(fmaxf(normS[ia] + nj - 2.f * dotv[a], 1e-4f));
        dkS[a][t] = dv;
        const bool neg = (labt != labsh[ia]) || (t == ia);  // (1-pos) incl. diagonal
        if (!neg) { int p = atomicAdd(&s_npos, 1); s_plist[p] = (a << 8) | t; }
        float m = neg ? dv : -CUDART_INF_F;                  // per-anchor max of negs
        #pragma unroll
        for (int off = 16; off; off >>= 1) m = fmaxf(m, __shfl_xor_sync(~0u, m, off));
        if (lane == 0) s_wmax[a][w] = m;
    }
    __syncthreads();
    if (t < NA) {
        float mm = s_wmax[t][0];
        #pragma unroll
        for (int q = 1; q < 8; q++) mm = fmaxf(mm, s_wmax[t][q]);
        s_maxneg[t] = mm;
    }
    __syncthreads();

    // ---- phase 2: warp-cooperative semi-hard scan over positives ----
    const int np = s_npos;
    float wsum = 0.f;
    for (int p = w; p < np; p += 8) {
        const int   e   = s_plist[p];
        const int   a   = e >> 8;
        const int   k   = e & 255;
        const int   ia  = ib + a;
        const int   la  = labsh[ia];
        const float dkk = dkS[a][k];
        float mg = CUDART_INF_F;       // min over negatives with d > dkk
        #pragma unroll
        for (int q = 0; q < 8; q++) {
            const int   jj = lane + 32 * q;          // one bank per lane
            const float dj = dkS[a][jj];
            const bool  ng = (labsh[jj] != la) || (jj == ia);
            mg = fminf(mg, (ng && dj > dkk) ? dj : CUDART_INF_F);
        }
        #pragma unroll
        for (int off = 16; off; off >>= 1) mg = fminf(mg, __shfl_xor_sync(~0u, mg, off));
        float v = (mg < CUDART_INF_F) ? (dkk - mg)           // semi-hard exists
                                      : (dkk - s_maxneg[a]); // fallback: easiest neg
        wsum += fmaxf(v + 1.0f, 0.f);                        // relu(semi_hard + MARGIN)
    }
    if (lane == 0 && wsum != 0.f) atomicAdd(&s_bsum, wsum);
    __syncthreads();

    // ---- last-block-done epilogue (single kernel) ----
    if (t == 0) {
        atomicAdd(&g_sum, s_bsum);
        atomicAdd(&g_cnt, (float)np);
        __threadfence();
        unsigned tk = atomicAdd(&g_ticket, 1u);
        if (tk == GRID - 1) {
            __threadfence();
            float s = atomicAdd(&g_sum, 0.f);
            float c = atomicAdd(&g_cnt, 0.f);
            out[0] = s / c;
            g_sum = 0.f;          // reset for next graph replay
            g_cnt = 0.f;
            __threadfence();
            g_ticket = 0u;
        }
    }
}

extern "C" void kernel_launch(void* const* d_in, const int* in_sizes, int n_in,
                              void* d_out, int out_size) {
    const float* emb    = (const float*)d_in[0];   // [256, 128] float32
    const int*   labraw = (const int*)d_in[1];     // [256] labels (int64/int32 detected)
    float* out = (float*)d_out;

    const int smem = 256 * ROWW * sizeof(float);   // 135168 B
    cudaFuncSetAttribute(triplet_fused, cudaFuncAttributeMaxDynamicSharedMemorySize, smem);
    triplet_fused<<<GRID, NT, smem>>>(emb, labraw, out);
}